// round 1
// baseline (speedup 1.0000x reference)
#include <cuda_runtime.h>
#include <math.h>

#define THREADS 256
#define OBS 127

// Shared-memory weight layout (float offsets). 16B alignment holds for all
// stride-1-accessed blocks (EN_W2, OA_W2, G_W2, M_W1, M_W2) so ptxas can
// emit LDS.128.
enum {
  EN_W1 = 0,            // 4*32  = 128
  EN_B1 = 128,          // 32
  EN_W2 = 160,          // 32*16 = 512
  EN_B2 = 672,          // 16
  OA_W1 = 688,          // 5*32  = 160
  OA_B1 = 848,          // 32
  OA_W2 = 880,          // 32*16 = 512
  OA_B2 = 1392,         // 16
  OA_G  = 1408,         // 16
  OA_BLN= 1424,         // 16
  G_W1  = 1440,         // 3*32  = 96
  G_B1  = 1536,         // 32
  G_W2  = 1568,         // 32*16 = 512
  G_B2  = 2080,         // 16
  G_G   = 2096,         // 16
  G_BLN = 2112,         // 16
  M_W1  = 2128,         // 48*32 = 1536
  M_B1  = 3664,         // 32
  M_W2  = 3696,         // 32*32 = 1024
  M_B2  = 4720,         // 32
  M_W3  = 4752,         // 32*2  = 64
  M_B3  = 4816,         // 2
  SW_TOTAL = 4818
};

__global__ void __launch_bounds__(THREADS)
actor_kernel(
    const float* __restrict__ s_input,
    const float* __restrict__ en_w1, const float* __restrict__ en_b1,
    const float* __restrict__ en_w2, const float* __restrict__ en_b2,
    const float* __restrict__ oa_w1, const float* __restrict__ oa_b1,
    const float* __restrict__ oa_w2, const float* __restrict__ oa_b2,
    const float* __restrict__ oa_g,  const float* __restrict__ oa_bln,
    const float* __restrict__ g_w1,  const float* __restrict__ g_b1,
    const float* __restrict__ g_w2,  const float* __restrict__ g_b2,
    const float* __restrict__ g_g,   const float* __restrict__ g_bln,
    const float* __restrict__ m_w1,  const float* __restrict__ m_b1,
    const float* __restrict__ m_w2,  const float* __restrict__ m_b2,
    const float* __restrict__ m_w3,  const float* __restrict__ m_b3,
    float* __restrict__ out, int B)
{
  __shared__ float sw[SW_TOTAL];
  const int tid = threadIdx.x;

  #define CP(off, src, n) \
    for (int i = tid; i < (n); i += THREADS) sw[(off) + i] = (src)[i];
  CP(EN_W1, en_w1, 128)  CP(EN_B1, en_b1, 32)
  CP(EN_W2, en_w2, 512)  CP(EN_B2, en_b2, 16)
  CP(OA_W1, oa_w1, 160)  CP(OA_B1, oa_b1, 32)
  CP(OA_W2, oa_w2, 512)  CP(OA_B2, oa_b2, 16)
  CP(OA_G,  oa_g,  16)   CP(OA_BLN, oa_bln, 16)
  CP(G_W1,  g_w1,  96)   CP(G_B1, g_b1, 32)
  CP(G_W2,  g_w2,  512)  CP(G_B2, g_b2, 16)
  CP(G_G,   g_g,   16)   CP(G_BLN, g_bln, 16)
  CP(M_W1,  m_w1,  1536) CP(M_B1, m_b1, 32)
  CP(M_W2,  m_w2,  1024) CP(M_B2, m_b2, 32)
  CP(M_W3,  m_w3,  64)   CP(M_B3, m_b3, 2)
  #undef CP
  __syncthreads();

  const int b = blockIdx.x * THREADS + tid;
  if (b >= B) return;

  const float* __restrict__ s = s_input + (size_t)b * OBS;

  // ---------------- self MLP: 4 -> 32 -> 16 ----------------
  float h[32];
  {
    const float x0 = s[0], x1 = s[1], x2 = s[2], x3 = s[3];
    #pragma unroll
    for (int j = 0; j < 32; j++) {
      float a = sw[EN_B1 + j];
      a = fmaf(x0, sw[EN_W1 +      j], a);
      a = fmaf(x1, sw[EN_W1 + 32 + j], a);
      a = fmaf(x2, sw[EN_W1 + 64 + j], a);
      a = fmaf(x3, sw[EN_W1 + 96 + j], a);
      h[j] = fmaxf(a, 0.0f);
    }
  }
  float self_out[16];
  #pragma unroll
  for (int k = 0; k < 16; k++) self_out[k] = sw[EN_B2 + k];
  #pragma unroll
  for (int i = 0; i < 32; i++) {
    const float hi = h[i];
    #pragma unroll
    for (int k = 0; k < 16; k++)
      self_out[k] = fmaf(hi, sw[EN_W2 + i * 16 + k], self_out[k]);
  }
  #pragma unroll
  for (int k = 0; k < 16; k++) self_out[k] = fmaxf(self_out[k], 0.0f);

  // ---------------- other-agent branch: 15 entities, online softmax ----------------
  float other_out[16];
  {
    float m = -1e30f, d = 0.0f;
    float acc[16];
    #pragma unroll
    for (int k = 0; k < 16; k++) acc[k] = 0.0f;

    #pragma unroll 1
    for (int n = 0; n < 15; n++) {
      const float i0 = s[4 + 2 * n];
      const float i1 = s[5 + 2 * n];
      const float i2 = s[34 + 2 * n];
      const float i3 = s[35 + 2 * n];
      const float i4 = s[64 + n];

      #pragma unroll
      for (int j = 0; j < 32; j++) {
        float a = sw[OA_B1 + j];
        a = fmaf(i0, sw[OA_W1 +       j], a);
        a = fmaf(i1, sw[OA_W1 + 32  + j], a);
        a = fmaf(i2, sw[OA_W1 + 64  + j], a);
        a = fmaf(i3, sw[OA_W1 + 96  + j], a);
        a = fmaf(i4, sw[OA_W1 + 128 + j], a);
        h[j] = fmaxf(a, 0.0f);
      }
      float e[16];
      #pragma unroll
      for (int k = 0; k < 16; k++) e[k] = sw[OA_B2 + k];
      #pragma unroll
      for (int i = 0; i < 32; i++) {
        const float hi = h[i];
        #pragma unroll
        for (int k = 0; k < 16; k++)
          e[k] = fmaf(hi, sw[OA_W2 + i * 16 + k], e[k]);
      }
      float sc = 0.0f;
      #pragma unroll
      for (int k = 0; k < 16; k++) {
        e[k] = fmaxf(e[k], 0.0f);
        sc = fmaf(self_out[k], e[k], sc);
      }
      sc *= 0.25f;  // 1/sqrt(16)

      const float mn = fmaxf(m, sc);
      const float f  = __expf(m - mn);
      const float p  = __expf(sc - mn);
      d = d * f + p;
      #pragma unroll
      for (int k = 0; k < 16; k++) acc[k] = fmaf(acc[k], f, p * e[k]);
      m = mn;
    }

    const float inv = 1.0f / d;
    float att[16], mu = 0.0f;
    #pragma unroll
    for (int k = 0; k < 16; k++) { att[k] = acc[k] * inv; mu += att[k]; }
    mu *= (1.0f / 16.0f);
    float var = 0.0f;
    #pragma unroll
    for (int k = 0; k < 16; k++) { const float t = att[k] - mu; var = fmaf(t, t, var); }
    var *= (1.0f / 16.0f);
    const float isd = rsqrtf(var + 1e-5f);
    #pragma unroll
    for (int k = 0; k < 16; k++)
      other_out[k] = fmaxf((att[k] - mu) * isd * sw[OA_G + k] + sw[OA_BLN + k], 0.0f);
  }

  // ---------------- food branch: 16 entities, online softmax ----------------
  float food_out[16];
  {
    float m = -1e30f, d = 0.0f;
    float acc[16];
    #pragma unroll
    for (int k = 0; k < 16; k++) acc[k] = 0.0f;

    #pragma unroll 1
    for (int n = 0; n < 16; n++) {
      const float i0 = s[79 + 3 * n];
      const float i1 = s[80 + 3 * n];
      const float i2 = s[81 + 3 * n];

      #pragma unroll
      for (int j = 0; j < 32; j++) {
        float a = sw[G_B1 + j];
        a = fmaf(i0, sw[G_W1 +      j], a);
        a = fmaf(i1, sw[G_W1 + 32 + j], a);
        a = fmaf(i2, sw[G_W1 + 64 + j], a);
        h[j] = fmaxf(a, 0.0f);
      }
      float e[16];
      #pragma unroll
      for (int k = 0; k < 16; k++) e[k] = sw[G_B2 + k];
      #pragma unroll
      for (int i = 0; i < 32; i++) {
        const float hi = h[i];
        #pragma unroll
        for (int k = 0; k < 16; k++)
          e[k] = fmaf(hi, sw[G_W2 + i * 16 + k], e[k]);
      }
      float sc = 0.0f;
      #pragma unroll
      for (int k = 0; k < 16; k++) {
        e[k] = fmaxf(e[k], 0.0f);
        sc = fmaf(self_out[k], e[k], sc);
      }
      sc *= 0.25f;

      const float mn = fmaxf(m, sc);
      const float f  = __expf(m - mn);
      const float p  = __expf(sc - mn);
      d = d * f + p;
      #pragma unroll
      for (int k = 0; k < 16; k++) acc[k] = fmaf(acc[k], f, p * e[k]);
      m = mn;
    }

    const float inv = 1.0f / d;
    float att[16], mu = 0.0f;
    #pragma unroll
    for (int k = 0; k < 16; k++) { att[k] = acc[k] * inv; mu += att[k]; }
    mu *= (1.0f / 16.0f);
    float var = 0.0f;
    #pragma unroll
    for (int k = 0; k < 16; k++) { const float t = att[k] - mu; var = fmaf(t, t, var); }
    var *= (1.0f / 16.0f);
    const float isd = rsqrtf(var + 1e-5f);
    #pragma unroll
    for (int k = 0; k < 16; k++)
      food_out[k] = fmaxf((att[k] - mu) * isd * sw[G_G + k] + sw[G_BLN + k], 0.0f);
  }

  // ---------------- merge head: concat(self, food, other) -> 32 -> 32 -> 2 ----------------
  float h1[32];
  #pragma unroll
  for (int j = 0; j < 32; j++) h1[j] = sw[M_B1 + j];
  #pragma unroll
  for (int i = 0; i < 16; i++) {
    const float v = self_out[i];
    #pragma unroll
    for (int j = 0; j < 32; j++) h1[j] = fmaf(v, sw[M_W1 + i * 32 + j], h1[j]);
  }
  #pragma unroll
  for (int i = 0; i < 16; i++) {
    const float v = food_out[i];
    #pragma unroll
    for (int j = 0; j < 32; j++) h1[j] = fmaf(v, sw[M_W1 + (16 + i) * 32 + j], h1[j]);
  }
  #pragma unroll
  for (int i = 0; i < 16; i++) {
    const float v = other_out[i];
    #pragma unroll
    for (int j = 0; j < 32; j++) h1[j] = fmaf(v, sw[M_W1 + (32 + i) * 32 + j], h1[j]);
  }
  #pragma unroll
  for (int j = 0; j < 32; j++) h1[j] = fmaxf(h1[j], 0.01f * h1[j]);  // leaky_relu

  float h2[32];
  #pragma unroll
  for (int j = 0; j < 32; j++) h2[j] = sw[M_B2 + j];
  #pragma unroll
  for (int i = 0; i < 32; i++) {
    const float v = h1[i];
    #pragma unroll
    for (int j = 0; j < 32; j++) h2[j] = fmaf(v, sw[M_W2 + i * 32 + j], h2[j]);
  }
  #pragma unroll
  for (int j = 0; j < 32; j++) h2[j] = fmaxf(h2[j], 0.01f * h2[j]);

  float o0 = sw[M_B3 + 0], o1 = sw[M_B3 + 1];
  #pragma unroll
  for (int i = 0; i < 32; i++) {
    o0 = fmaf(h2[i], sw[M_W3 + i * 2 + 0], o0);
    o1 = fmaf(h2[i], sw[M_W3 + i * 2 + 1], o1);
  }
  out[(size_t)b * 2 + 0] = tanhf(o0);
  out[(size_t)b * 2 + 1] = tanhf(o1);
}

extern "C" void kernel_launch(void* const* d_in, const int* in_sizes, int n_in,
                              void* d_out, int out_size)
{
  const float* s = (const float*)d_in[0];
  const int B = in_sizes[0] / OBS;
  const int blocks = (B + THREADS - 1) / THREADS;

  actor_kernel<<<blocks, THREADS>>>(
      s,
      (const float*)d_in[1],  (const float*)d_in[2],
      (const float*)d_in[3],  (const float*)d_in[4],
      (const float*)d_in[5],  (const float*)d_in[6],
      (const float*)d_in[7],  (const float*)d_in[8],
      (const float*)d_in[9],  (const float*)d_in[10],
      (const float*)d_in[11], (const float*)d_in[12],
      (const float*)d_in[13], (const float*)d_in[14],
      (const float*)d_in[15], (const float*)d_in[16],
      (const float*)d_in[17], (const float*)d_in[18],
      (const float*)d_in[19], (const float*)d_in[20],
      (const float*)d_in[21], (const float*)d_in[22],
      (float*)d_out, B);
}

// round 2
// speedup vs baseline: 4.7763x; 4.7763x over previous
#include <cuda_runtime.h>
#include <math.h>

#define THREADS 256
#define OBS 127

// Shared-memory weight layout (float offsets).
enum {
  EN_W1 = 0,            // 4*32  = 128
  EN_B1 = 128,          // 32
  EN_W2 = 160,          // 32*16 = 512
  EN_B2 = 672,          // 16
  OA_W1 = 688,          // 5*32  = 160
  OA_B1 = 848,          // 32
  OA_W2 = 880,          // 32*16 = 512
  OA_B2 = 1392,         // 16
  OA_G  = 1408,         // 16
  OA_BLN= 1424,         // 16
  G_W1  = 1440,         // 3*32  = 96
  G_B1  = 1536,         // 32
  G_W2  = 1568,         // 32*16 = 512
  G_B2  = 2080,         // 16
  G_G   = 2096,         // 16
  G_BLN = 2112,         // 16
  M_W1  = 2128,         // 48*32 = 1536
  M_B1  = 3664,         // 32
  M_W2  = 3696,         // 32*32 = 1024
  M_B2  = 4720,         // 32
  M_W3  = 4752,         // 32*2  = 64
  M_B3  = 4816,         // 2
  SW_TOTAL = 4818
};

__global__ void __launch_bounds__(THREADS, 2)
actor_kernel(
    const float* __restrict__ s_input,
    const float* __restrict__ en_w1, const float* __restrict__ en_b1,
    const float* __restrict__ en_w2, const float* __restrict__ en_b2,
    const float* __restrict__ oa_w1, const float* __restrict__ oa_b1,
    const float* __restrict__ oa_w2, const float* __restrict__ oa_b2,
    const float* __restrict__ oa_g,  const float* __restrict__ oa_bln,
    const float* __restrict__ g_w1,  const float* __restrict__ g_b1,
    const float* __restrict__ g_w2,  const float* __restrict__ g_b2,
    const float* __restrict__ g_g,   const float* __restrict__ g_bln,
    const float* __restrict__ m_w1,  const float* __restrict__ m_b1,
    const float* __restrict__ m_w2,  const float* __restrict__ m_b2,
    const float* __restrict__ m_w3,  const float* __restrict__ m_b3,
    float* __restrict__ out, int B)
{
  __shared__ float sw[SW_TOTAL];
  const int tid = threadIdx.x;

  #define CP(off, src, n) \
    for (int i = tid; i < (n); i += THREADS) sw[(off) + i] = (src)[i];
  CP(EN_W1, en_w1, 128)  CP(EN_B1, en_b1, 32)
  CP(EN_W2, en_w2, 512)  CP(EN_B2, en_b2, 16)
  CP(OA_W1, oa_w1, 160)  CP(OA_B1, oa_b1, 32)
  CP(OA_W2, oa_w2, 512)  CP(OA_B2, oa_b2, 16)
  CP(OA_G,  oa_g,  16)   CP(OA_BLN, oa_bln, 16)
  CP(G_W1,  g_w1,  96)   CP(G_B1, g_b1, 32)
  CP(G_W2,  g_w2,  512)  CP(G_B2, g_b2, 16)
  CP(G_G,   g_g,   16)   CP(G_BLN, g_bln, 16)
  CP(M_W1,  m_w1,  1536) CP(M_B1, m_b1, 32)
  CP(M_W2,  m_w2,  1024) CP(M_B2, m_b2, 32)
  CP(M_W3,  m_w3,  64)   CP(M_B3, m_b3, 2)
  #undef CP
  __syncthreads();

  const int b = blockIdx.x * THREADS + tid;
  if (b >= B) return;

  const float* __restrict__ s = s_input + (size_t)b * OBS;

  // ---------------- self MLP: 4 -> 32 -> 16 (fused: no h[] array) ----------------
  float self_out[16];
  {
    const float x0 = s[0], x1 = s[1], x2 = s[2], x3 = s[3];
    #pragma unroll
    for (int k = 0; k < 16; k++) self_out[k] = sw[EN_B2 + k];
    #pragma unroll 4
    for (int j = 0; j < 32; j++) {
      float a = sw[EN_B1 + j];
      a = fmaf(x0, sw[EN_W1 +      j], a);
      a = fmaf(x1, sw[EN_W1 + 32 + j], a);
      a = fmaf(x2, sw[EN_W1 + 64 + j], a);
      a = fmaf(x3, sw[EN_W1 + 96 + j], a);
      a = fmaxf(a, 0.0f);
      #pragma unroll
      for (int k = 0; k < 16; k++)
        self_out[k] = fmaf(a, sw[EN_W2 + j * 16 + k], self_out[k]);
    }
    #pragma unroll
    for (int k = 0; k < 16; k++) self_out[k] = fmaxf(self_out[k], 0.0f);
  }

  // ---------------- other-agent branch: 15 entities, online softmax ----------------
  float other_out[16];
  {
    float m = -1e30f, d = 0.0f;
    float acc[16];
    #pragma unroll
    for (int k = 0; k < 16; k++) acc[k] = 0.0f;

    #pragma unroll 1
    for (int n = 0; n < 15; n++) {
      const float i0 = s[4 + 2 * n];
      const float i1 = s[5 + 2 * n];
      const float i2 = s[34 + 2 * n];
      const float i3 = s[35 + 2 * n];
      const float i4 = s[64 + n];

      float e[16];
      #pragma unroll
      for (int k = 0; k < 16; k++) e[k] = sw[OA_B2 + k];
      #pragma unroll 4
      for (int j = 0; j < 32; j++) {
        float a = sw[OA_B1 + j];
        a = fmaf(i0, sw[OA_W1 +       j], a);
        a = fmaf(i1, sw[OA_W1 + 32  + j], a);
        a = fmaf(i2, sw[OA_W1 + 64  + j], a);
        a = fmaf(i3, sw[OA_W1 + 96  + j], a);
        a = fmaf(i4, sw[OA_W1 + 128 + j], a);
        a = fmaxf(a, 0.0f);
        #pragma unroll
        for (int k = 0; k < 16; k++)
          e[k] = fmaf(a, sw[OA_W2 + j * 16 + k], e[k]);
      }
      float sc = 0.0f;
      #pragma unroll
      for (int k = 0; k < 16; k++) {
        e[k] = fmaxf(e[k], 0.0f);
        sc = fmaf(self_out[k], e[k], sc);
      }
      sc *= 0.25f;  // 1/sqrt(16)

      const float mn = fmaxf(m, sc);
      const float f  = __expf(m - mn);
      const float p  = __expf(sc - mn);
      d = d * f + p;
      #pragma unroll
      for (int k = 0; k < 16; k++) acc[k] = fmaf(acc[k], f, p * e[k]);
      m = mn;
    }

    const float inv = 1.0f / d;
    float mu = 0.0f;
    #pragma unroll
    for (int k = 0; k < 16; k++) { acc[k] *= inv; mu += acc[k]; }
    mu *= (1.0f / 16.0f);
    float var = 0.0f;
    #pragma unroll
    for (int k = 0; k < 16; k++) { const float t = acc[k] - mu; var = fmaf(t, t, var); }
    var *= (1.0f / 16.0f);
    const float isd = rsqrtf(var + 1e-5f);
    #pragma unroll
    for (int k = 0; k < 16; k++)
      other_out[k] = fmaxf((acc[k] - mu) * isd * sw[OA_G + k] + sw[OA_BLN + k], 0.0f);
  }

  // ---------------- food branch: 16 entities, online softmax ----------------
  float food_out[16];
  {
    float m = -1e30f, d = 0.0f;
    float acc[16];
    #pragma unroll
    for (int k = 0; k < 16; k++) acc[k] = 0.0f;

    #pragma unroll 1
    for (int n = 0; n < 16; n++) {
      const float i0 = s[79 + 3 * n];
      const float i1 = s[80 + 3 * n];
      const float i2 = s[81 + 3 * n];

      float e[16];
      #pragma unroll
      for (int k = 0; k < 16; k++) e[k] = sw[G_B2 + k];
      #pragma unroll 4
      for (int j = 0; j < 32; j++) {
        float a = sw[G_B1 + j];
        a = fmaf(i0, sw[G_W1 +      j], a);
        a = fmaf(i1, sw[G_W1 + 32 + j], a);
        a = fmaf(i2, sw[G_W1 + 64 + j], a);
        a = fmaxf(a, 0.0f);
        #pragma unroll
        for (int k = 0; k < 16; k++)
          e[k] = fmaf(a, sw[G_W2 + j * 16 + k], e[k]);
      }
      float sc = 0.0f;
      #pragma unroll
      for (int k = 0; k < 16; k++) {
        e[k] = fmaxf(e[k], 0.0f);
        sc = fmaf(self_out[k], e[k], sc);
      }
      sc *= 0.25f;

      const float mn = fmaxf(m, sc);
      const float f  = __expf(m - mn);
      const float p  = __expf(sc - mn);
      d = d * f + p;
      #pragma unroll
      for (int k = 0; k < 16; k++) acc[k] = fmaf(acc[k], f, p * e[k]);
      m = mn;
    }

    const float inv = 1.0f / d;
    float mu = 0.0f;
    #pragma unroll
    for (int k = 0; k < 16; k++) { acc[k] *= inv; mu += acc[k]; }
    mu *= (1.0f / 16.0f);
    float var = 0.0f;
    #pragma unroll
    for (int k = 0; k < 16; k++) { const float t = acc[k] - mu; var = fmaf(t, t, var); }
    var *= (1.0f / 16.0f);
    const float isd = rsqrtf(var + 1e-5f);
    #pragma unroll
    for (int k = 0; k < 16; k++)
      food_out[k] = fmaxf((acc[k] - mu) * isd * sw[G_G + k] + sw[G_BLN + k], 0.0f);
  }

  // ---------------- merge head: concat(self, food, other) -> 32 -> 32 -> 2 ----------------
  float h1[32];
  #pragma unroll
  for (int j = 0; j < 32; j++) h1[j] = sw[M_B1 + j];
  #pragma unroll 4
  for (int i = 0; i < 16; i++) {
    const float v = self_out[i];
    #pragma unroll
    for (int j = 0; j < 32; j++) h1[j] = fmaf(v, sw[M_W1 + i * 32 + j], h1[j]);
  }
  #pragma unroll 4
  for (int i = 0; i < 16; i++) {
    const float v = food_out[i];
    #pragma unroll
    for (int j = 0; j < 32; j++) h1[j] = fmaf(v, sw[M_W1 + (16 + i) * 32 + j], h1[j]);
  }
  #pragma unroll 4
  for (int i = 0; i < 16; i++) {
    const float v = other_out[i];
    #pragma unroll
    for (int j = 0; j < 32; j++) h1[j] = fmaf(v, sw[M_W1 + (32 + i) * 32 + j], h1[j]);
  }
  #pragma unroll
  for (int j = 0; j < 32; j++) h1[j] = fmaxf(h1[j], 0.01f * h1[j]);  // leaky_relu

  // Second layer: accumulate into h2 reusing self_out/food_out register space
  // via a fresh array (h1 is consumed column-wise).
  float h2[32];
  #pragma unroll
  for (int j = 0; j < 32; j++) h2[j] = sw[M_B2 + j];
  #pragma unroll 4
  for (int i = 0; i < 32; i++) {
    const float v = h1[i];
    #pragma unroll
    for (int j = 0; j < 32; j++) h2[j] = fmaf(v, sw[M_W2 + i * 32 + j], h2[j]);
  }

  float o0 = sw[M_B3 + 0], o1 = sw[M_B3 + 1];
  #pragma unroll
  for (int i = 0; i < 32; i++) {
    const float v = fmaxf(h2[i], 0.01f * h2[i]);
    o0 = fmaf(v, sw[M_W3 + i * 2 + 0], o0);
    o1 = fmaf(v, sw[M_W3 + i * 2 + 1], o1);
  }
  out[(size_t)b * 2 + 0] = tanhf(o0);
  out[(size_t)b * 2 + 1] = tanhf(o1);
}

extern "C" void kernel_launch(void* const* d_in, const int* in_sizes, int n_in,
                              void* d_out, int out_size)
{
  const float* s = (const float*)d_in[0];
  const int B = in_sizes[0] / OBS;
  const int blocks = (B + THREADS - 1) / THREADS;

  actor_kernel<<<blocks, THREADS>>>(
      s,
      (const float*)d_in[1],  (const float*)d_in[2],
      (const float*)d_in[3],  (const float*)d_in[4],
      (const float*)d_in[5],  (const float*)d_in[6],
      (const float*)d_in[7],  (const float*)d_in[8],
      (const float*)d_in[9],  (const float*)d_in[10],
      (const float*)d_in[11], (const float*)d_in[12],
      (const float*)d_in[13], (const float*)d_in[14],
      (const float*)d_in[15], (const float*)d_in[16],
      (const float*)d_in[17], (const float*)d_in[18],
      (const float*)d_in[19], (const float*)d_in[20],
      (const float*)d_in[21], (const float*)d_in[22],
      (float*)d_out, B);
}

// round 3
// speedup vs baseline: 6.9887x; 1.4632x over previous
#include <cuda_runtime.h>
#include <math.h>

#define THREADS 256
#define OBS 127

typedef unsigned long long u64;

__device__ __forceinline__ u64 ffma2(u64 a, u64 b, u64 c) {
  u64 d; asm("fma.rn.f32x2 %0, %1, %2, %3;" : "=l"(d) : "l"(a), "l"(b), "l"(c)); return d;
}
__device__ __forceinline__ u64 fmul2(u64 a, u64 b) {
  u64 d; asm("mul.rn.f32x2 %0, %1, %2;" : "=l"(d) : "l"(a), "l"(b)); return d;
}
__device__ __forceinline__ u64 pack2(float lo, float hi) {
  u64 d; asm("mov.b64 %0, {%1, %2};" : "=l"(d) : "f"(lo), "f"(hi)); return d;
}
__device__ __forceinline__ void unpack2(u64 v, float& lo, float& hi) {
  asm("mov.b64 {%0, %1}, %2;" : "=f"(lo), "=f"(hi) : "l"(v));
}
__device__ __forceinline__ u64 bcast2(float x) { return pack2(x, x); }
__device__ __forceinline__ u64 relu2(u64 v) {
  float a, b; unpack2(v, a, b);
  return pack2(fmaxf(a, 0.0f), fmaxf(b, 0.0f));
}

// Shared layout (float offsets; every base is a multiple of 4 floats = 16B).
enum {
  ENW1P = 0,      // 16 jp * 12  (b,w0..w3 pairs, 2 pad)  = 192
  OAW1P = 192,    // 16 jp * 12  (b,w0..w4 pairs)         = 192
  GW1P  = 384,    // 16 jp * 8   (b,w0..w2 pairs)         = 128
  EN_W2 = 512,    // 32*16
  EN_B2 = 1024,   // 16
  OA_W2 = 1040,   // 32*16
  OA_B2 = 1552,   // 16
  OA_G  = 1568,   // 16
  OA_BLN= 1584,   // 16
  G_W2  = 1600,   // 32*16
  G_B2  = 2112,   // 16
  G_G   = 2128,   // 16
  G_BLN = 2144,   // 16
  M_W1  = 2160,   // 48*32
  M_B1  = 3696,   // 32
  M_W2  = 3728,   // 32*32
  M_B2  = 4752,   // 32
  M_W3  = 4784,   // 32*2
  M_B3  = 4848,   // 2 (8B aligned: 4848*4 % 8 == 0)
  SW_TOTAL = 4852
};

__global__ void __launch_bounds__(THREADS, 2)
actor_kernel(
    const float* __restrict__ s_input,
    const float* __restrict__ en_w1, const float* __restrict__ en_b1,
    const float* __restrict__ en_w2, const float* __restrict__ en_b2,
    const float* __restrict__ oa_w1, const float* __restrict__ oa_b1,
    const float* __restrict__ oa_w2, const float* __restrict__ oa_b2,
    const float* __restrict__ oa_g,  const float* __restrict__ oa_bln,
    const float* __restrict__ g_w1,  const float* __restrict__ g_b1,
    const float* __restrict__ g_w2,  const float* __restrict__ g_b2,
    const float* __restrict__ g_g,   const float* __restrict__ g_bln,
    const float* __restrict__ m_w1,  const float* __restrict__ m_b1,
    const float* __restrict__ m_w2,  const float* __restrict__ m_b2,
    const float* __restrict__ m_w3,  const float* __restrict__ m_b3,
    float* __restrict__ out, int B)
{
  __shared__ float sw[SW_TOTAL];
  const int tid = threadIdx.x;

  // ---- repacked layer-1 blocks: per hidden-pair jp, interleaved (j,j+1) ----
  for (int idx = tid; idx < 192; idx += THREADS) {           // EN: 4 inputs
    int jp = idx / 12, r = idx % 12, slot = r >> 1, half = r & 1, j = 2 * jp + half;
    float v = 0.0f;
    if (slot == 0) v = en_b1[j];
    else if (slot <= 4) v = en_w1[(slot - 1) * 32 + j];
    sw[ENW1P + idx] = v;
  }
  for (int idx = tid; idx < 192; idx += THREADS) {           // OA: 5 inputs
    int jp = idx / 12, r = idx % 12, slot = r >> 1, half = r & 1, j = 2 * jp + half;
    sw[OAW1P + idx] = (slot == 0) ? oa_b1[j] : oa_w1[(slot - 1) * 32 + j];
  }
  for (int idx = tid; idx < 128; idx += THREADS) {           // G: 3 inputs
    int jp = idx / 8, r = idx % 8, slot = r >> 1, half = r & 1, j = 2 * jp + half;
    sw[GW1P + idx] = (slot == 0) ? g_b1[j] : g_w1[(slot - 1) * 32 + j];
  }

  #define CP(off, src, n) \
    for (int i = tid; i < (n); i += THREADS) sw[(off) + i] = (src)[i];
  CP(EN_W2, en_w2, 512)  CP(EN_B2, en_b2, 16)
  CP(OA_W2, oa_w2, 512)  CP(OA_B2, oa_b2, 16)
  CP(OA_G,  oa_g,  16)   CP(OA_BLN, oa_bln, 16)
  CP(G_W2,  g_w2,  512)  CP(G_B2, g_b2, 16)
  CP(G_G,   g_g,   16)   CP(G_BLN, g_bln, 16)
  CP(M_W1,  m_w1,  1536) CP(M_B1, m_b1, 32)
  CP(M_W2,  m_w2,  1024) CP(M_B2, m_b2, 32)
  CP(M_W3,  m_w3,  64)   CP(M_B3, m_b3, 2)
  #undef CP
  __syncthreads();

  const int b = blockIdx.x * THREADS + tid;
  if (b >= B) return;

  const float* __restrict__ s = s_input + (size_t)b * OBS;

  // ================= self MLP: 4 -> 32 -> 16, packed =================
  u64 selfp[8];
  {
    const ulonglong2* b2 = (const ulonglong2*)&sw[EN_B2];
    #pragma unroll
    for (int t = 0; t < 4; t++) { selfp[2 * t] = b2[t].x; selfp[2 * t + 1] = b2[t].y; }
    const u64 p0 = bcast2(s[0]), p1 = bcast2(s[1]), p2 = bcast2(s[2]), p3 = bcast2(s[3]);
    #pragma unroll 4
    for (int jp = 0; jp < 16; jp++) {
      const ulonglong2* r = (const ulonglong2*)&sw[ENW1P + jp * 12];
      ulonglong2 q0 = r[0], q1 = r[1], q2 = r[2];
      u64 a = q0.x;
      a = ffma2(p0, q0.y, a);
      a = ffma2(p1, q1.x, a);
      a = ffma2(p2, q1.y, a);
      a = ffma2(p3, q2.x, a);
      float a0, a1; unpack2(a, a0, a1);
      const u64 A0 = bcast2(fmaxf(a0, 0.0f));
      const u64 A1 = bcast2(fmaxf(a1, 0.0f));
      const ulonglong2* w = (const ulonglong2*)&sw[EN_W2 + jp * 32];
      #pragma unroll
      for (int q = 0; q < 4; q++) {
        ulonglong2 wv = w[q];
        selfp[2 * q]     = ffma2(A0, wv.x, selfp[2 * q]);
        selfp[2 * q + 1] = ffma2(A0, wv.y, selfp[2 * q + 1]);
      }
      #pragma unroll
      for (int q = 0; q < 4; q++) {
        ulonglong2 wv = w[4 + q];
        selfp[2 * q]     = ffma2(A1, wv.x, selfp[2 * q]);
        selfp[2 * q + 1] = ffma2(A1, wv.y, selfp[2 * q + 1]);
      }
    }
    #pragma unroll
    for (int t = 0; t < 8; t++) selfp[t] = relu2(selfp[t]);
  }

  // ================= other-agent branch: 15 entities =================
  u64 otherp[8];
  {
    float m = -1e30f, d = 0.0f;
    u64 acc[8];
    #pragma unroll
    for (int t = 0; t < 8; t++) acc[t] = 0ULL;

    #pragma unroll 1
    for (int n = 0; n < 15; n++) {
      const u64 p0 = bcast2(s[4 + 2 * n]);
      const u64 p1 = bcast2(s[5 + 2 * n]);
      const u64 p2 = bcast2(s[34 + 2 * n]);
      const u64 p3 = bcast2(s[35 + 2 * n]);
      const u64 p4 = bcast2(s[64 + n]);

      u64 e[8];
      {
        const ulonglong2* b2 = (const ulonglong2*)&sw[OA_B2];
        #pragma unroll
        for (int t = 0; t < 4; t++) { e[2 * t] = b2[t].x; e[2 * t + 1] = b2[t].y; }
      }
      #pragma unroll 4
      for (int jp = 0; jp < 16; jp++) {
        const ulonglong2* r = (const ulonglong2*)&sw[OAW1P + jp * 12];
        ulonglong2 q0 = r[0], q1 = r[1], q2 = r[2];
        u64 a = q0.x;
        a = ffma2(p0, q0.y, a);
        a = ffma2(p1, q1.x, a);
        a = ffma2(p2, q1.y, a);
        a = ffma2(p3, q2.x, a);
        a = ffma2(p4, q2.y, a);
        float a0, a1; unpack2(a, a0, a1);
        const u64 A0 = bcast2(fmaxf(a0, 0.0f));
        const u64 A1 = bcast2(fmaxf(a1, 0.0f));
        const ulonglong2* w = (const ulonglong2*)&sw[OA_W2 + jp * 32];
        #pragma unroll
        for (int q = 0; q < 4; q++) {
          ulonglong2 wv = w[q];
          e[2 * q]     = ffma2(A0, wv.x, e[2 * q]);
          e[2 * q + 1] = ffma2(A0, wv.y, e[2 * q + 1]);
        }
        #pragma unroll
        for (int q = 0; q < 4; q++) {
          ulonglong2 wv = w[4 + q];
          e[2 * q]     = ffma2(A1, wv.x, e[2 * q]);
          e[2 * q + 1] = ffma2(A1, wv.y, e[2 * q + 1]);
        }
      }
      u64 sc2 = 0ULL;
      #pragma unroll
      for (int t = 0; t < 8; t++) {
        e[t] = relu2(e[t]);
        sc2 = ffma2(selfp[t], e[t], sc2);
      }
      float slo, shi; unpack2(sc2, slo, shi);
      const float sc = (slo + shi) * 0.25f;   // 1/sqrt(16)

      const float mn = fmaxf(m, sc);
      const float f  = __expf(m - mn);
      const float p  = __expf(sc - mn);
      d = d * f + p;
      const u64 F = bcast2(f), P = bcast2(p);
      #pragma unroll
      for (int t = 0; t < 8; t++) acc[t] = ffma2(acc[t], F, fmul2(P, e[t]));
      m = mn;
    }

    const float inv = 1.0f / d;
    float att[16], mu = 0.0f;
    #pragma unroll
    for (int t = 0; t < 8; t++) {
      float a0, a1; unpack2(acc[t], a0, a1);
      att[2 * t] = a0 * inv; att[2 * t + 1] = a1 * inv;
      mu += att[2 * t] + att[2 * t + 1];
    }
    mu *= (1.0f / 16.0f);
    float var = 0.0f;
    #pragma unroll
    for (int k = 0; k < 16; k++) { const float t = att[k] - mu; var = fmaf(t, t, var); }
    var *= (1.0f / 16.0f);
    const float isd = rsqrtf(var + 1e-5f);
    const u64* gp  = (const u64*)&sw[OA_G];
    const u64* blp = (const u64*)&sw[OA_BLN];
    #pragma unroll
    for (int t = 0; t < 8; t++) {
      const u64 y = pack2((att[2 * t] - mu) * isd, (att[2 * t + 1] - mu) * isd);
      otherp[t] = relu2(ffma2(y, gp[t], blp[t]));
    }
  }

  // ================= food branch: 16 entities =================
  u64 foodp[8];
  {
    float m = -1e30f, d = 0.0f;
    u64 acc[8];
    #pragma unroll
    for (int t = 0; t < 8; t++) acc[t] = 0ULL;

    #pragma unroll 1
    for (int n = 0; n < 16; n++) {
      const u64 p0 = bcast2(s[79 + 3 * n]);
      const u64 p1 = bcast2(s[80 + 3 * n]);
      const u64 p2 = bcast2(s[81 + 3 * n]);

      u64 e[8];
      {
        const ulonglong2* b2 = (const ulonglong2*)&sw[G_B2];
        #pragma unroll
        for (int t = 0; t < 4; t++) { e[2 * t] = b2[t].x; e[2 * t + 1] = b2[t].y; }
      }
      #pragma unroll 4
      for (int jp = 0; jp < 16; jp++) {
        const ulonglong2* r = (const ulonglong2*)&sw[GW1P + jp * 8];
        ulonglong2 q0 = r[0], q1 = r[1];
        u64 a = q0.x;
        a = ffma2(p0, q0.y, a);
        a = ffma2(p1, q1.x, a);
        a = ffma2(p2, q1.y, a);
        float a0, a1; unpack2(a, a0, a1);
        const u64 A0 = bcast2(fmaxf(a0, 0.0f));
        const u64 A1 = bcast2(fmaxf(a1, 0.0f));
        const ulonglong2* w = (const ulonglong2*)&sw[G_W2 + jp * 32];
        #pragma unroll
        for (int q = 0; q < 4; q++) {
          ulonglong2 wv = w[q];
          e[2 * q]     = ffma2(A0, wv.x, e[2 * q]);
          e[2 * q + 1] = ffma2(A0, wv.y, e[2 * q + 1]);
        }
        #pragma unroll
        for (int q = 0; q < 4; q++) {
          ulonglong2 wv = w[4 + q];
          e[2 * q]     = ffma2(A1, wv.x, e[2 * q]);
          e[2 * q + 1] = ffma2(A1, wv.y, e[2 * q + 1]);
        }
      }
      u64 sc2 = 0ULL;
      #pragma unroll
      for (int t = 0; t < 8; t++) {
        e[t] = relu2(e[t]);
        sc2 = ffma2(selfp[t], e[t], sc2);
      }
      float slo, shi; unpack2(sc2, slo, shi);
      const float sc = (slo + shi) * 0.25f;

      const float mn = fmaxf(m, sc);
      const float f  = __expf(m - mn);
      const float p  = __expf(sc - mn);
      d = d * f + p;
      const u64 F = bcast2(f), P = bcast2(p);
      #pragma unroll
      for (int t = 0; t < 8; t++) acc[t] = ffma2(acc[t], F, fmul2(P, e[t]));
      m = mn;
    }

    const float inv = 1.0f / d;
    float att[16], mu = 0.0f;
    #pragma unroll
    for (int t = 0; t < 8; t++) {
      float a0, a1; unpack2(acc[t], a0, a1);
      att[2 * t] = a0 * inv; att[2 * t + 1] = a1 * inv;
      mu += att[2 * t] + att[2 * t + 1];
    }
    mu *= (1.0f / 16.0f);
    float var = 0.0f;
    #pragma unroll
    for (int k = 0; k < 16; k++) { const float t = att[k] - mu; var = fmaf(t, t, var); }
    var *= (1.0f / 16.0f);
    const float isd = rsqrtf(var + 1e-5f);
    const u64* gp  = (const u64*)&sw[G_G];
    const u64* blp = (const u64*)&sw[G_BLN];
    #pragma unroll
    for (int t = 0; t < 8; t++) {
      const u64 y = pack2((att[2 * t] - mu) * isd, (att[2 * t + 1] - mu) * isd);
      foodp[t] = relu2(ffma2(y, gp[t], blp[t]));
    }
  }

  // ================= merge head: 48 -> 32 -> 32 -> 2, packed =================
  u64 h1[16];
  {
    const ulonglong2* bm = (const ulonglong2*)&sw[M_B1];
    #pragma unroll
    for (int t = 0; t < 8; t++) { h1[2 * t] = bm[t].x; h1[2 * t + 1] = bm[t].y; }
  }
  // segments in merged order: self (rows 0-15), food (16-31), other (32-47)
  #pragma unroll 1
  for (int seg = 0; seg < 3; seg++) {
    const u64* src = (seg == 0) ? selfp : (seg == 1) ? foodp : otherp;
    const int rowbase = seg * 16;
    #pragma unroll 2
    for (int t = 0; t < 8; t++) {
      float v0, v1; unpack2(src[t], v0, v1);
      const u64 V0 = bcast2(v0), V1 = bcast2(v1);
      const ulonglong2* w0 = (const ulonglong2*)&sw[M_W1 + (rowbase + 2 * t) * 32];
      #pragma unroll
      for (int q = 0; q < 8; q++) {
        ulonglong2 wv = w0[q];
        h1[2 * q]     = ffma2(V0, wv.x, h1[2 * q]);
        h1[2 * q + 1] = ffma2(V0, wv.y, h1[2 * q + 1]);
      }
      const ulonglong2* w1p = (const ulonglong2*)&sw[M_W1 + (rowbase + 2 * t + 1) * 32];
      #pragma unroll
      for (int q = 0; q < 8; q++) {
        ulonglong2 wv = w1p[q];
        h1[2 * q]     = ffma2(V1, wv.x, h1[2 * q]);
        h1[2 * q + 1] = ffma2(V1, wv.y, h1[2 * q + 1]);
      }
    }
  }

  u64 h2[16];
  {
    const ulonglong2* bm = (const ulonglong2*)&sw[M_B2];
    #pragma unroll
    for (int t = 0; t < 8; t++) { h2[2 * t] = bm[t].x; h2[2 * t + 1] = bm[t].y; }
  }
  #pragma unroll 2
  for (int t = 0; t < 16; t++) {
    float v0, v1; unpack2(h1[t], v0, v1);
    v0 = fmaxf(v0, 0.01f * v0);            // leaky_relu
    v1 = fmaxf(v1, 0.01f * v1);
    const u64 V0 = bcast2(v0), V1 = bcast2(v1);
    const ulonglong2* w0 = (const ulonglong2*)&sw[M_W2 + (2 * t) * 32];
    #pragma unroll
    for (int q = 0; q < 8; q++) {
      ulonglong2 wv = w0[q];
      h2[2 * q]     = ffma2(V0, wv.x, h2[2 * q]);
      h2[2 * q + 1] = ffma2(V0, wv.y, h2[2 * q + 1]);
    }
    const ulonglong2* w1p = (const ulonglong2*)&sw[M_W2 + (2 * t + 1) * 32];
    #pragma unroll
    for (int q = 0; q < 8; q++) {
      ulonglong2 wv = w1p[q];
      h2[2 * q]     = ffma2(V1, wv.x, h2[2 * q]);
      h2[2 * q + 1] = ffma2(V1, wv.y, h2[2 * q + 1]);
    }
  }

  u64 o2 = *(const u64*)&sw[M_B3];
  const u64* w3 = (const u64*)&sw[M_W3];   // pair i = (w_i0, w_i1)
  #pragma unroll
  for (int t = 0; t < 16; t++) {
    float v0, v1; unpack2(h2[t], v0, v1);
    v0 = fmaxf(v0, 0.01f * v0);
    v1 = fmaxf(v1, 0.01f * v1);
    o2 = ffma2(bcast2(v0), w3[2 * t], o2);
    o2 = ffma2(bcast2(v1), w3[2 * t + 1], o2);
  }
  float o0, o1; unpack2(o2, o0, o1);
  float2 res; res.x = tanhf(o0); res.y = tanhf(o1);
  *(float2*)&out[(size_t)b * 2] = res;
}

extern "C" void kernel_launch(void* const* d_in, const int* in_sizes, int n_in,
                              void* d_out, int out_size)
{
  const float* s = (const float*)d_in[0];
  const int B = in_sizes[0] / OBS;
  const int blocks = (B + THREADS - 1) / THREADS;

  actor_kernel<<<blocks, THREADS>>>(
      s,
      (const float*)d_in[1],  (const float*)d_in[2],
      (const float*)d_in[3],  (const float*)d_in[4],
      (const float*)d_in[5],  (const float*)d_in[6],
      (const float*)d_in[7],  (const float*)d_in[8],
      (const float*)d_in[9],  (const float*)d_in[10],
      (const float*)d_in[11], (const float*)d_in[12],
      (const float*)d_in[13], (const float*)d_in[14],
      (const float*)d_in[15], (const float*)d_in[16],
      (const float*)d_in[17], (const float*)d_in[18],
      (const float*)d_in[19], (const float*)d_in[20],
      (const float*)d_in[21], (const float*)d_in[22],
      (float*)d_out, B);
}